// round 13
// baseline (speedup 1.0000x reference)
#include <cuda_runtime.h>

// RayTransform: local_pos = (pos - trans) @ R, local_dir = dir @ R
// R = exp(skew(rot_vec)). N = 16777216 rays, ~805 MB HBM traffic.
//
// Warp-autonomous (no block barriers), .cs streaming loads, .wt
// write-through stores (full-line streaming writes skip L2 dirty-line
// bookkeeping -> less read/writeback churn at the DRAM scheduler).

#define THREADS 256
#define WARPS (THREADS / 32)
#define F4_PER_WARP 96                       // 128 rays per warp per stream
#define F4_PER_BLOCK (WARPS * F4_PER_WARP)   // 768

__global__ void __launch_bounds__(THREADS, 6)
ray_transform_kernel(const float4* __restrict__ pos,
                     const float4* __restrict__ dir,
                     float4* __restrict__ out_pos,
                     float4* __restrict__ out_dir,
                     const float* __restrict__ rot_vec,
                     const float* __restrict__ trans) {
    __shared__ float4 buf[WARPS][F4_PER_WARP];

    const int t = threadIdx.x;
    const int w = t >> 5;
    const int l = t & 31;

    // global chunk base for this warp (in float4 units, per stream)
    const size_t cbase = (size_t)blockIdx.x * F4_PER_BLOCK + w * F4_PER_WARP;

    // ---- all 6 coalesced LDG.128.CS in flight ----
    float4 p0 = __ldcs(pos + cbase + l);
    float4 p1 = __ldcs(pos + cbase + l + 32);
    float4 p2 = __ldcs(pos + cbase + l + 64);
    float4 d0 = __ldcs(dir + cbase + l);
    float4 d1 = __ldcs(dir + cbase + l + 32);
    float4 d2 = __ldcs(dir + cbase + l + 64);

    // ---- per-thread Rodrigues (uniform loads, broadcast) ----
    const float rx = rot_vec[0], ry = rot_vec[1], rz = rot_vec[2];
    const float theta2 = rx * rx + ry * ry + rz * rz;
    const float theta = sqrtf(theta2);
    float a, b;
    if (theta < 1e-8f) {
        a = 1.0f - theta2 / 6.0f;
        b = 0.5f - theta2 / 24.0f;
    } else {
        a = sinf(theta) / theta;
        b = (1.0f - cosf(theta)) / theta2;
    }
    const float R0 = 1.0f - b * (ry * ry + rz * rz);
    const float R1 = -a * rz + b * rx * ry;
    const float R2 =  a * ry + b * rx * rz;
    const float R3 =  a * rz + b * rx * ry;
    const float R4 = 1.0f - b * (rx * rx + rz * rz);
    const float R5 = -a * rx + b * ry * rz;
    const float R6 = -a * ry + b * rx * rz;
    const float R7 =  a * rx + b * ry * rz;
    const float R8 = 1.0f - b * (rx * rx + ry * ry);
    const float t0 = trans[0], t1 = trans[1], t2 = trans[2];

    float4* wb = buf[w];

    // ================= POS =================
    wb[l] = p0;  wb[l + 32] = p1;  wb[l + 64] = p2;
    __syncwarp();
    {
        // lane l owns f4 3l..3l+2 (4 rays); word stride 12 conflict-free.
        float4 a4 = wb[l * 3], b4 = wb[l * 3 + 1], c4 = wb[l * 3 + 2];
        float px[4] = {a4.x, a4.w, b4.z, c4.y};
        float py[4] = {a4.y, b4.x, b4.w, c4.z};
        float pz[4] = {a4.z, b4.y, c4.x, c4.w};
        float ox[4], oy[4], oz[4];
#pragma unroll
        for (int k = 0; k < 4; k++) {
            float x = px[k] - t0;
            float y = py[k] - t1;
            float z = pz[k] - t2;
            ox[k] = fmaf(x, R0, fmaf(y, R3, z * R6));
            oy[k] = fmaf(x, R1, fmaf(y, R4, z * R7));
            oz[k] = fmaf(x, R2, fmaf(y, R5, z * R8));
        }
        // same-lane write-back: no barrier needed between read and write
        wb[l * 3]     = make_float4(ox[0], oy[0], oz[0], ox[1]);
        wb[l * 3 + 1] = make_float4(oy[1], oz[1], ox[2], oy[2]);
        wb[l * 3 + 2] = make_float4(oz[2], ox[3], oy[3], oz[3]);
    }
    __syncwarp();
    __stwt(out_pos + cbase + l,      wb[l]);
    __stwt(out_pos + cbase + l + 32, wb[l + 32]);
    __stwt(out_pos + cbase + l + 64, wb[l + 64]);

    // ================= DIR =================
    // overwrite is same-lane as the reads just above (4l-stride both) -> safe
    wb[l] = d0;  wb[l + 32] = d1;  wb[l + 64] = d2;
    __syncwarp();
    {
        float4 a4 = wb[l * 3], b4 = wb[l * 3 + 1], c4 = wb[l * 3 + 2];
        float px[4] = {a4.x, a4.w, b4.z, c4.y};
        float py[4] = {a4.y, b4.x, b4.w, c4.z};
        float pz[4] = {a4.z, b4.y, c4.x, c4.w};
        float ox[4], oy[4], oz[4];
#pragma unroll
        for (int k = 0; k < 4; k++) {
            float x = px[k];
            float y = py[k];
            float z = pz[k];
            ox[k] = fmaf(x, R0, fmaf(y, R3, z * R6));
            oy[k] = fmaf(x, R1, fmaf(y, R4, z * R7));
            oz[k] = fmaf(x, R2, fmaf(y, R5, z * R8));
        }
        wb[l * 3]     = make_float4(ox[0], oy[0], oz[0], ox[1]);
        wb[l * 3 + 1] = make_float4(oy[1], oz[1], ox[2], oy[2]);
        wb[l * 3 + 2] = make_float4(oz[2], ox[3], oy[3], oz[3]);
    }
    __syncwarp();
    __stwt(out_dir + cbase + l,      wb[l]);
    __stwt(out_dir + cbase + l + 32, wb[l + 32]);
    __stwt(out_dir + cbase + l + 64, wb[l + 64]);
}

extern "C" void kernel_launch(void* const* d_in, const int* in_sizes, int n_in,
                              void* d_out, int out_size) {
    const float* pos = (const float*)d_in[0];      // [N,3]
    const float* dir = (const float*)d_in[1];      // [N,3]
    const float* rot_vec = (const float*)d_in[2];  // [3]
    const float* trans = (const float*)d_in[3];    // [3]

    int n_f4 = in_sizes[0] / 4;  // N*3/4 float4 per stream = 12582912
    float* out = (float*)d_out;
    float* out_pos = out;
    float* out_dir = out + (size_t)out_size / 2;

    int blocks = n_f4 / F4_PER_BLOCK;  // 12582912 / 768 = 16384, exact
    ray_transform_kernel<<<blocks, THREADS>>>(
        (const float4*)pos, (const float4*)dir,
        (float4*)out_pos, (float4*)out_dir, rot_vec, trans);
}

// round 16
// speedup vs baseline: 1.0212x; 1.0212x over previous
#include <cuda_runtime.h>

// RayTransform: local_pos = (pos - trans) @ R, local_dir = dir @ R
// R = exp(skew(rot_vec)). N = 16777216 rays, ~805 MB HBM traffic.
//
// FINAL (R12 revert): warp-autonomous (no block barriers) + .cs streaming
// hints on all bulk traffic. Six structural variants all converge to
// ~6.4-6.5 TB/s => effective HBM ceiling for a 50/50 R/W streaming mix;
// this is the best-measured configuration (119.9 us total).

#define THREADS 256
#define WARPS (THREADS / 32)
#define F4_PER_WARP 96                       // 128 rays per warp per stream
#define F4_PER_BLOCK (WARPS * F4_PER_WARP)   // 768

__global__ void __launch_bounds__(THREADS, 6)
ray_transform_kernel(const float4* __restrict__ pos,
                     const float4* __restrict__ dir,
                     float4* __restrict__ out_pos,
                     float4* __restrict__ out_dir,
                     const float* __restrict__ rot_vec,
                     const float* __restrict__ trans) {
    __shared__ float4 buf[WARPS][F4_PER_WARP];

    const int t = threadIdx.x;
    const int w = t >> 5;
    const int l = t & 31;

    // global chunk base for this warp (in float4 units, per stream)
    const size_t cbase = (size_t)blockIdx.x * F4_PER_BLOCK + w * F4_PER_WARP;

    // ---- all 6 coalesced LDG.128.CS in flight ----
    float4 p0 = __ldcs(pos + cbase + l);
    float4 p1 = __ldcs(pos + cbase + l + 32);
    float4 p2 = __ldcs(pos + cbase + l + 64);
    float4 d0 = __ldcs(dir + cbase + l);
    float4 d1 = __ldcs(dir + cbase + l + 32);
    float4 d2 = __ldcs(dir + cbase + l + 64);

    // ---- per-thread Rodrigues (uniform loads, broadcast) ----
    const float rx = rot_vec[0], ry = rot_vec[1], rz = rot_vec[2];
    const float theta2 = rx * rx + ry * ry + rz * rz;
    const float theta = sqrtf(theta2);
    float a, b;
    if (theta < 1e-8f) {
        a = 1.0f - theta2 / 6.0f;
        b = 0.5f - theta2 / 24.0f;
    } else {
        a = sinf(theta) / theta;
        b = (1.0f - cosf(theta)) / theta2;
    }
    const float R0 = 1.0f - b * (ry * ry + rz * rz);
    const float R1 = -a * rz + b * rx * ry;
    const float R2 =  a * ry + b * rx * rz;
    const float R3 =  a * rz + b * rx * ry;
    const float R4 = 1.0f - b * (rx * rx + rz * rz);
    const float R5 = -a * rx + b * ry * rz;
    const float R6 = -a * ry + b * rx * rz;
    const float R7 =  a * rx + b * ry * rz;
    const float R8 = 1.0f - b * (rx * rx + ry * ry);
    const float t0 = trans[0], t1 = trans[1], t2 = trans[2];

    float4* wb = buf[w];

    // ================= POS =================
    wb[l] = p0;  wb[l + 32] = p1;  wb[l + 64] = p2;
    __syncwarp();
    {
        // lane l owns f4 3l..3l+2 (4 rays); word stride 12 conflict-free.
        float4 a4 = wb[l * 3], b4 = wb[l * 3 + 1], c4 = wb[l * 3 + 2];
        float px[4] = {a4.x, a4.w, b4.z, c4.y};
        float py[4] = {a4.y, b4.x, b4.w, c4.z};
        float pz[4] = {a4.z, b4.y, c4.x, c4.w};
        float ox[4], oy[4], oz[4];
#pragma unroll
        for (int k = 0; k < 4; k++) {
            float x = px[k] - t0;
            float y = py[k] - t1;
            float z = pz[k] - t2;
            ox[k] = fmaf(x, R0, fmaf(y, R3, z * R6));
            oy[k] = fmaf(x, R1, fmaf(y, R4, z * R7));
            oz[k] = fmaf(x, R2, fmaf(y, R5, z * R8));
        }
        // same-lane write-back: no barrier needed between read and write
        wb[l * 3]     = make_float4(ox[0], oy[0], oz[0], ox[1]);
        wb[l * 3 + 1] = make_float4(oy[1], oz[1], ox[2], oy[2]);
        wb[l * 3 + 2] = make_float4(oz[2], ox[3], oy[3], oz[3]);
    }
    __syncwarp();
    __stcs(out_pos + cbase + l,      wb[l]);
    __stcs(out_pos + cbase + l + 32, wb[l + 32]);
    __stcs(out_pos + cbase + l + 64, wb[l + 64]);

    // ================= DIR =================
    // overwrite is same-lane as the reads just above (4l-stride both) -> safe
    wb[l] = d0;  wb[l + 32] = d1;  wb[l + 64] = d2;
    __syncwarp();
    {
        float4 a4 = wb[l * 3], b4 = wb[l * 3 + 1], c4 = wb[l * 3 + 2];
        float px[4] = {a4.x, a4.w, b4.z, c4.y};
        float py[4] = {a4.y, b4.x, b4.w, c4.z};
        float pz[4] = {a4.z, b4.y, c4.x, c4.w};
        float ox[4], oy[4], oz[4];
#pragma unroll
        for (int k = 0; k < 4; k++) {
            float x = px[k];
            float y = py[k];
            float z = pz[k];
            ox[k] = fmaf(x, R0, fmaf(y, R3, z * R6));
            oy[k] = fmaf(x, R1, fmaf(y, R4, z * R7));
            oz[k] = fmaf(x, R2, fmaf(y, R5, z * R8));
        }
        wb[l * 3]     = make_float4(ox[0], oy[0], oz[0], ox[1]);
        wb[l * 3 + 1] = make_float4(oy[1], oz[1], ox[2], oy[2]);
        wb[l * 3 + 2] = make_float4(oz[2], ox[3], oy[3], oz[3]);
    }
    __syncwarp();
    __stcs(out_dir + cbase + l,      wb[l]);
    __stcs(out_dir + cbase + l + 32, wb[l + 32]);
    __stcs(out_dir + cbase + l + 64, wb[l + 64]);
}

extern "C" void kernel_launch(void* const* d_in, const int* in_sizes, int n_in,
                              void* d_out, int out_size) {
    const float* pos = (const float*)d_in[0];      // [N,3]
    const float* dir = (const float*)d_in[1];      // [N,3]
    const float* rot_vec = (const float*)d_in[2];  // [3]
    const float* trans = (const float*)d_in[3];    // [3]

    int n_f4 = in_sizes[0] / 4;  // N*3/4 float4 per stream = 12582912
    float* out = (float*)d_out;
    float* out_pos = out;
    float* out_dir = out + (size_t)out_size / 2;

    int blocks = n_f4 / F4_PER_BLOCK;  // 12582912 / 768 = 16384, exact
    ray_transform_kernel<<<blocks, THREADS>>>(
        (const float4*)pos, (const float4*)dir,
        (float4*)out_pos, (float4*)out_dir, rot_vec, trans);
}